// round 1
// baseline (speedup 1.0000x reference)
#include <cuda_runtime.h>
#include <math.h>

// RMSD_20126216749374: Kabsch-aligned MSE.
// loss = mean over (B,N,3) of (x_centered @ R - y_centered)^2
// Using R orthogonal:  sum = Sxx + Syy - 2*tr(R^T C),
// and Kabsch:          tr(R^T C) = s0 + s1 + sign(det C)*s2
// where s_i = singular values of C = x_c^T y_c (3x3), computed via the
// closed-form trigonometric eigensolver of A = C^T C. One streaming pass.

constexpr int NB = 8192;   // batches
constexpr int NP = 512;    // points per batch (3 floats each)

__device__ float g_batch_loss[NB];

__global__ __launch_bounds__(256)
void rmsd_stats_kernel(const float* __restrict__ inp, const float* __restrict__ tgt)
{
    const int b = blockIdx.x;
    const int t = threadIdx.x;

    // Per batch: 512 points * 3 floats = 1536 floats = 768 float2.
    // Thread t handles points 2t and 2t+1 -> float2 indices 3t..3t+2 (8B aligned).
    const float2* xp = reinterpret_cast<const float2*>(inp) + (size_t)b * 768 + 3 * t;
    const float2* yp = reinterpret_cast<const float2*>(tgt) + (size_t)b * 768 + 3 * t;

    float2 xa = xp[0], xb = xp[1], xc = xp[2];
    float2 ya = yp[0], yb = yp[1], yc = yp[2];

    float x0[3] = {xa.x, xa.y, xb.x};
    float x1[3] = {xb.y, xc.x, xc.y};
    float y0[3] = {ya.x, ya.y, yb.x};
    float y1[3] = {yb.y, yc.x, yc.y};

    // 17 reduction values: [0:3) sum x, [3:6) sum y, [6] sum|x|^2, [7] sum|y|^2,
    // [8:17) sum x_d * y_e  (C raw, row-major d,e)
    float v[17];
#pragma unroll
    for (int d = 0; d < 3; d++) {
        v[d]     = x0[d] + x1[d];
        v[3 + d] = y0[d] + y1[d];
    }
    v[6] = x0[0]*x0[0] + x0[1]*x0[1] + x0[2]*x0[2]
         + x1[0]*x1[0] + x1[1]*x1[1] + x1[2]*x1[2];
    v[7] = y0[0]*y0[0] + y0[1]*y0[1] + y0[2]*y0[2]
         + y1[0]*y1[0] + y1[1]*y1[1] + y1[2]*y1[2];
#pragma unroll
    for (int d = 0; d < 3; d++)
#pragma unroll
        for (int e = 0; e < 3; e++)
            v[8 + 3*d + e] = x0[d]*y0[e] + x1[d]*y1[e];

    // Warp tree-reduce all 17 values
#pragma unroll
    for (int i = 0; i < 17; i++) {
#pragma unroll
        for (int o = 16; o > 0; o >>= 1)
            v[i] += __shfl_down_sync(0xffffffffu, v[i], o);
    }

    __shared__ float red[8][17];
    __shared__ float fin[17];
    const int wid = t >> 5, lane = t & 31;
    if (lane == 0) {
#pragma unroll
        for (int i = 0; i < 17; i++) red[wid][i] = v[i];
    }
    __syncthreads();
    if (t < 17) {
        float s = 0.f;
#pragma unroll
        for (int w = 0; w < 8; w++) s += red[w][t];
        fin[t] = s;
    }
    __syncthreads();

    if (t == 0) {
        const float n = (float)NP;
        const float invn = 1.f / n;
        float mx[3], my[3];
#pragma unroll
        for (int d = 0; d < 3; d++) { mx[d] = fin[d] * invn; my[d] = fin[3 + d] * invn; }

        // Centered covariance C[d][e] = sum x_d y_e - n * mx_d * my_e
        float C[3][3];
#pragma unroll
        for (int d = 0; d < 3; d++)
#pragma unroll
            for (int e = 0; e < 3; e++)
                C[d][e] = fin[8 + 3*d + e] - n * mx[d] * my[e];

        float sxx = fin[6] - n * (mx[0]*mx[0] + mx[1]*mx[1] + mx[2]*mx[2]);
        float syy = fin[7] - n * (my[0]*my[0] + my[1]*my[1] + my[2]*my[2]);

        // A = C^T C (symmetric 3x3): a00,a11,a22 diag; a01,a02,a12 off-diag
        float a00 = C[0][0]*C[0][0] + C[1][0]*C[1][0] + C[2][0]*C[2][0];
        float a11 = C[0][1]*C[0][1] + C[1][1]*C[1][1] + C[2][1]*C[2][1];
        float a22 = C[0][2]*C[0][2] + C[1][2]*C[1][2] + C[2][2]*C[2][2];
        float a01 = C[0][0]*C[0][1] + C[1][0]*C[1][1] + C[2][0]*C[2][1];
        float a02 = C[0][0]*C[0][2] + C[1][0]*C[1][2] + C[2][0]*C[2][2];
        float a12 = C[0][1]*C[0][2] + C[1][1]*C[1][2] + C[2][1]*C[2][2];

        // Closed-form eigenvalues of symmetric 3x3 (trig method)
        float q  = (a00 + a11 + a22) * (1.f / 3.f);
        float p1 = a01*a01 + a02*a02 + a12*a12;
        float b00 = a00 - q, b11 = a11 - q, b22 = a22 - q;
        float p2 = b00*b00 + b11*b11 + b22*b22 + 2.f * p1;
        float p  = sqrtf(fmaxf(p2, 1e-30f) * (1.f / 6.f));
        float ip = 1.f / p;
        float detB = ( b00 * (b11*b22 - a12*a12)
                     - a01 * (a01*b22 - a12*a02)
                     + a02 * (a01*a12 - b11*a02) ) * (ip * ip * ip);
        float r = fminf(fmaxf(0.5f * detB, -1.f), 1.f);
        float phi = acosf(r) * (1.f / 3.f);
        float e0 = q + 2.f * p * cosf(phi);                          // largest
        float e2 = q + 2.f * p * cosf(phi + 2.0943951023931953f);    // smallest
        float e1 = 3.f * q - e0 - e2;                                // middle

        float s0 = sqrtf(fmaxf(e0, 0.f));
        float s1 = sqrtf(fmaxf(e1, 0.f));
        float s2 = sqrtf(fmaxf(e2, 0.f));

        float detC = C[0][0]*(C[1][1]*C[2][2] - C[1][2]*C[2][1])
                   - C[0][1]*(C[1][0]*C[2][2] - C[1][2]*C[2][0])
                   + C[0][2]*(C[1][0]*C[2][1] - C[1][1]*C[2][0]);
        float sgn = (detC < 0.f) ? -1.f : 1.f;

        g_batch_loss[b] = sxx + syy - 2.f * (s0 + s1 + sgn * s2);
    }
}

__global__ __launch_bounds__(256)
void rmsd_reduce_kernel(float* __restrict__ out)
{
    const int t = threadIdx.x;
    double s = 0.0;
    for (int i = t; i < NB; i += 256) s += (double)g_batch_loss[i];

#pragma unroll
    for (int o = 16; o > 0; o >>= 1)
        s += __shfl_down_sync(0xffffffffu, s, o);

    __shared__ double sm[8];
    const int wid = t >> 5, lane = t & 31;
    if (lane == 0) sm[wid] = s;
    __syncthreads();
    if (t == 0) {
        double tot = 0.0;
#pragma unroll
        for (int w = 0; w < 8; w++) tot += sm[w];
        out[0] = (float)(tot / ((double)NB * (double)NP * 3.0));
    }
}

extern "C" void kernel_launch(void* const* d_in, const int* in_sizes, int n_in,
                              void* d_out, int out_size)
{
    const float* inp = (const float*)d_in[0];
    const float* tgt = (const float*)d_in[1];
    float* out = (float*)d_out;

    rmsd_stats_kernel<<<NB, 256>>>(inp, tgt);
    rmsd_reduce_kernel<<<1, 256>>>(out);
}

// round 2
// speedup vs baseline: 1.9710x; 1.9710x over previous
#include <cuda_runtime.h>
#include <math.h>

// RMSD (Kabsch-aligned MSE), fully fused single kernel.
// loss_b = Sxx + Syy - 2*(s0 + s1 + sign(det C)*s2),
// s_i = singular values of C = x_c^T y_c via closed-form trig eigensolver of C^T C.
// One warp per batch; per-block partial -> last-block deterministic reduce.

constexpr int NB  = 8192;   // batches
constexpr int NP  = 512;    // points per batch
constexpr int WPB = 8;      // warps (batches) per block
constexpr int NBLK = NB / WPB;  // 1024 blocks

__device__ double       g_partial[NBLK];
__device__ unsigned int g_count = 0;

__device__ __forceinline__ float kabsch_loss(const float* fin)
{
    const float n = (float)NP;
    const float invn = 1.f / n;
    float mx[3], my[3];
#pragma unroll
    for (int d = 0; d < 3; d++) { mx[d] = fin[d] * invn; my[d] = fin[3 + d] * invn; }

    float C[3][3];
#pragma unroll
    for (int d = 0; d < 3; d++)
#pragma unroll
        for (int e = 0; e < 3; e++)
            C[d][e] = fin[8 + 3*d + e] - n * mx[d] * my[e];

    float sxx = fin[6] - n * (mx[0]*mx[0] + mx[1]*mx[1] + mx[2]*mx[2]);
    float syy = fin[7] - n * (my[0]*my[0] + my[1]*my[1] + my[2]*my[2]);

    // A = C^T C (symmetric)
    float a00 = C[0][0]*C[0][0] + C[1][0]*C[1][0] + C[2][0]*C[2][0];
    float a11 = C[0][1]*C[0][1] + C[1][1]*C[1][1] + C[2][1]*C[2][1];
    float a22 = C[0][2]*C[0][2] + C[1][2]*C[1][2] + C[2][2]*C[2][2];
    float a01 = C[0][0]*C[0][1] + C[1][0]*C[1][1] + C[2][0]*C[2][1];
    float a02 = C[0][0]*C[0][2] + C[1][0]*C[1][2] + C[2][0]*C[2][2];
    float a12 = C[0][1]*C[0][2] + C[1][1]*C[1][2] + C[2][1]*C[2][2];

    // Closed-form eigenvalues (trig method)
    float q  = (a00 + a11 + a22) * (1.f / 3.f);
    float p1 = a01*a01 + a02*a02 + a12*a12;
    float b00 = a00 - q, b11 = a11 - q, b22 = a22 - q;
    float p2 = b00*b00 + b11*b11 + b22*b22 + 2.f * p1;
    float p  = sqrtf(fmaxf(p2, 1e-30f) * (1.f / 6.f));
    float ip = 1.f / p;
    float detB = ( b00 * (b11*b22 - a12*a12)
                 - a01 * (a01*b22 - a12*a02)
                 + a02 * (a01*a12 - b11*a02) ) * (ip * ip * ip);
    float r = fminf(fmaxf(0.5f * detB, -1.f), 1.f);
    float phi = acosf(r) * (1.f / 3.f);
    float e0 = q + 2.f * p * cosf(phi);
    float e2 = q + 2.f * p * cosf(phi + 2.0943951023931953f);
    float e1 = 3.f * q - e0 - e2;

    float s0 = sqrtf(fmaxf(e0, 0.f));
    float s1 = sqrtf(fmaxf(e1, 0.f));
    float s2 = sqrtf(fmaxf(e2, 0.f));

    float detC = C[0][0]*(C[1][1]*C[2][2] - C[1][2]*C[2][1])
               - C[0][1]*(C[1][0]*C[2][2] - C[1][2]*C[2][0])
               + C[0][2]*(C[1][0]*C[2][1] - C[1][1]*C[2][0]);
    float sgn = (detC < 0.f) ? -1.f : 1.f;

    return sxx + syy - 2.f * (s0 + s1 + sgn * s2);
}

__global__ __launch_bounds__(256)
void rmsd_fused_kernel(const float4* __restrict__ x4, const float4* __restrict__ y4,
                       float* __restrict__ out)
{
    const int w    = threadIdx.x >> 5;
    const int lane = threadIdx.x & 31;
    const int b    = blockIdx.x * WPB + w;

    // Per batch: 512 pts * 3 floats = 1536 floats = 384 float4.
    // Lane handles 4 point-groups of 4 points: group g = k*32+lane -> float4[3g..3g+2].
    const size_t base = (size_t)b * 384;

    float v[17];
#pragma unroll
    for (int i = 0; i < 17; i++) v[i] = 0.f;

#pragma unroll
    for (int k = 0; k < 4; k++) {
        const int g = k * 32 + lane;
        const float4* xp = x4 + base + 3 * g;
        const float4* yp = y4 + base + 3 * g;
        float4 xa = xp[0], xb = xp[1], xc = xp[2];
        float4 ya = yp[0], yb = yp[1], yc = yp[2];

        float X[4][3] = {{xa.x, xa.y, xa.z}, {xa.w, xb.x, xb.y},
                         {xb.z, xb.w, xc.x}, {xc.y, xc.z, xc.w}};
        float Y[4][3] = {{ya.x, ya.y, ya.z}, {ya.w, yb.x, yb.y},
                         {yb.z, yb.w, yc.x}, {yc.y, yc.z, yc.w}};
#pragma unroll
        for (int pnt = 0; pnt < 4; pnt++) {
#pragma unroll
            for (int d = 0; d < 3; d++) {
                v[d]     += X[pnt][d];
                v[3 + d] += Y[pnt][d];
            }
            v[6] += X[pnt][0]*X[pnt][0] + X[pnt][1]*X[pnt][1] + X[pnt][2]*X[pnt][2];
            v[7] += Y[pnt][0]*Y[pnt][0] + Y[pnt][1]*Y[pnt][1] + Y[pnt][2]*Y[pnt][2];
#pragma unroll
            for (int d = 0; d < 3; d++)
#pragma unroll
                for (int e = 0; e < 3; e++)
                    v[8 + 3*d + e] += X[pnt][d] * Y[pnt][e];
        }
    }

    // Warp tree-reduce all 17 values
#pragma unroll
    for (int i = 0; i < 17; i++) {
#pragma unroll
        for (int o = 16; o > 0; o >>= 1)
            v[i] += __shfl_down_sync(0xffffffffu, v[i], o);
    }

    __shared__ float warp_loss[WPB];
    __shared__ int   is_last;
    if (lane == 0) warp_loss[w] = kabsch_loss(v);
    __syncthreads();

    if (threadIdx.x == 0) {
        double s = 0.0;
#pragma unroll
        for (int i = 0; i < WPB; i++) s += (double)warp_loss[i];
        g_partial[blockIdx.x] = s;
        __threadfence();
        unsigned done = atomicAdd(&g_count, 1u);
        is_last = (done == NBLK - 1) ? 1 : 0;
    }
    __syncthreads();

    if (is_last) {
        __threadfence();  // make all g_partial stores visible
        const int t = threadIdx.x;
        // 1024 partials, 256 threads, 4 each — fixed order, deterministic.
        volatile double* gp = g_partial;
        double s = 0.0;
#pragma unroll
        for (int i = 0; i < NBLK / 256; i++) s += gp[t + i * 256];

#pragma unroll
        for (int o = 16; o > 0; o >>= 1)
            s += __shfl_down_sync(0xffffffffu, s, o);

        __shared__ double sm[8];
        if (lane == 0) sm[w] = s;
        __syncthreads();
        if (t == 0) {
            double tot = 0.0;
#pragma unroll
            for (int i = 0; i < 8; i++) tot += sm[i];
            out[0] = (float)(tot / ((double)NB * (double)NP * 3.0));
            g_count = 0;  // reset for next graph replay
        }
    }
}

extern "C" void kernel_launch(void* const* d_in, const int* in_sizes, int n_in,
                              void* d_out, int out_size)
{
    const float4* inp = (const float4*)d_in[0];
    const float4* tgt = (const float4*)d_in[1];
    float* out = (float*)d_out;

    rmsd_fused_kernel<<<NBLK, 256>>>(inp, tgt, out);
}